// round 8
// baseline (speedup 1.0000x reference)
#include <cuda_runtime.h>
#include <cstdint>
#include <cstddef>

// CTC loss (keras ctc_batch_cost semantics) on GB300.
// B=256, T=1024, C=128 (blank=127), U=100, S=2U+1=201.
//
//   - one block per batch element, 2 warps
//   - warp 0: forward alpha   t = 0 .. 511
//   - warp 1: backward gamma  t = 1023 .. 512 (emission-inclusive)
//   - combine P = sum_s alpha_511[s] * beta_511[s]
//   - linear-prob domain, per-lane log2 offsets, EXACT power-of-2 renorm
//     via clamped exponent extraction (no MUFU on the renorm path)
//   - lane l owns 7 states; band exchange via shfl
//   - 8-deep cp.async smem ring of 512B prob rows per warp

namespace {
constexpr int B_ = 256;
constexpr int T_ = 1024;
constexpr int C_ = 128;
constexpr int U_ = 100;
constexpr int S_ = 2 * U_ + 1;      // 201
constexpr int BLANK_ = C_ - 1;      // 127
constexpr float EPS_ = 1e-7f;
constexpr int DPF = 8;              // cp.async ring depth
constexpr int TMID = (T_ - 2) / 2;  // 511
// renorm threshold: must exceed 2^-88 so the exponent build stays in [1,254]
constexpr float RENORM_MIN = 1e-26f;
}

__device__ __forceinline__ float ex2f(float x){ float y; asm("ex2.approx.f32 %0, %1;" : "=f"(y) : "f"(x)); return y; }
__device__ __forceinline__ float lg2f(float x){ float y; asm("lg2.approx.f32 %0, %1;" : "=f"(y) : "f"(x)); return y; }

// exact renorm: returns inv = 2^-eo (power of two) such that m*inv ~ [2^40,2^41).
// invariant: (a *= inv) together with (o += eo) preserves a*2^o.
// exponent field clamped to [1,254] -> inv always positive finite.
__device__ __forceinline__ float exp_scale(float m, int& eo){
    int ei = (__float_as_int(m) >> 23) & 0xff;
    int eb = 294 - ei;                       // target: m*2^(eb-127) ~ 2^40
    eb = (eb < 1) ? 1 : (eb > 254 ? 254 : eb);
    eo = 127 - eb;                           // inv = 2^(eb-127) = 2^-eo
    return __int_as_float(eb << 23);
}

__device__ __forceinline__ void cp_async16(void* sdst, const void* gsrc){
    uint32_t s;
    asm("{ .reg .u64 t; cvta.to.shared.u64 t, %1; cvt.u32.u64 %0, t; }" : "=r"(s) : "l"(sdst));
    asm volatile("cp.async.cg.shared.global [%0], [%1], 16;" :: "r"(s), "l"(gsrc));
}
__device__ __forceinline__ void cp_commit(){ asm volatile("cp.async.commit_group;" ::: "memory"); }
__device__ __forceinline__ void cp_wait7(){ asm volatile("cp.async.wait_group 7;" ::: "memory"); }
__device__ __forceinline__ void cp_waitall(){ asm volatile("cp.async.wait_all;" ::: "memory"); }

__global__ void __launch_bounds__(64)
ctc_fb_kernel(const float* __restrict__ yp, const int* __restrict__ yt,
              const int* __restrict__ llen, float* __restrict__ out)
{
    __shared__ float ring[2][DPF][C_];   // staged prob rows, per warp
    __shared__ float dbuf[32][8];        // beta_511 per lane: 7 values + log2 offset

    const int b    = blockIdx.x;
    const int warp = threadIdx.x >> 5;
    const int lane = threadIdx.x & 31;
    const float* __restrict__ row0 = yp + (size_t)b * T_ * C_;
    const int*   __restrict__ lab  = yt + b * U_;
    const int L = llen[b];

    const int s0 = lane * 7;
    int   cls[7];
    float sk[7];
    bool  valid[7];
    #pragma unroll
    for (int j = 0; j < 7; ++j) {
        int s = s0 + j;
        valid[j] = (s < S_);
        int c = BLANK_;
        if (valid[j] && (s & 1)) c = lab[s >> 1];
        cls[j] = c;
        if (warp == 0) {
            sk[j] = (valid[j] && (s & 1) && s >= 3 && lab[s >> 1] != lab[(s >> 1) - 1]) ? 1.f : 0.f;
        } else {
            int s2 = s + 2;
            sk[j] = ((s2 < S_) && (s2 & 1) && lab[s2 >> 1] != lab[(s2 >> 1) - 1]) ? 1.f : 0.f;
        }
    }

    float a[7];
    float o = 0.f;   // per-lane log2 offset (integer-valued): true value = a[j]*2^o

    if (warp == 0) {
        // =========================== FORWARD ===========================
        #pragma unroll
        for (int d = 0; d < DPF; ++d) {
            cp_async16(&ring[0][d][lane * 4], row0 + d * C_ + lane * 4);
            cp_commit();
        }
        cp_wait7(); __syncwarp();
        {
            const float* rw = &ring[0][0][0];
            #pragma unroll
            for (int j = 0; j < 7; ++j) {
                float w = valid[j] ? rw[cls[j]] + EPS_ : 0.f;
                a[j] = (s0 + j <= 1) ? w : 0.f;
            }
        }

        for (int t = 1; t <= TMID; ++t) {
            const int pf = t + DPF - 1;             // <= 518 < T
            cp_async16(&ring[0][pf & (DPF - 1)][lane * 4], row0 + (size_t)pf * C_ + lane * 4);
            cp_commit();
            cp_wait7(); __syncwarp();

            const float* rw = &ring[0][t & (DPF - 1)][0];
            float w[7];
            #pragma unroll
            for (int j = 0; j < 7; ++j)
                w[j] = valid[j] ? rw[cls[j]] + EPS_ : 0.f;

            float am1 = __shfl_up_sync(0xffffffffu, a[6], 1);
            float am2 = __shfl_up_sync(0xffffffffu, a[5], 1);
            float op  = __shfl_up_sync(0xffffffffu, o, 1);
            if (lane == 0) { am1 = 0.f; am2 = 0.f; op = o; }
            float r = ex2f(fminf(op - o, 80.f));
            am1 *= r; am2 *= r;

            float n[7];
            n[0] = (a[0] + am1  + sk[0] * am2 ) * w[0];
            n[1] = (a[1] + a[0] + sk[1] * am1 ) * w[1];
            #pragma unroll
            for (int j = 2; j < 7; ++j)
                n[j] = (a[j] + a[j-1] + sk[j] * a[j-2]) * w[j];

            float m = n[0];
            #pragma unroll
            for (int j = 1; j < 7; ++j) m = fmaxf(m, n[j]);

            if (m > RENORM_MIN) {
                int eo; float inv = exp_scale(m, eo);
                #pragma unroll
                for (int j = 0; j < 7; ++j) a[j] = n[j] * inv;
                o += (float)eo;
            } else {
                #pragma unroll
                for (int j = 0; j < 7; ++j) a[j] = n[j];
                o = op;                                  // frame adoption
            }
        }
        cp_waitall();
    } else {
        // =========================== BACKWARD ==========================
        #pragma unroll
        for (int d = 0; d < DPF; ++d) {
            const int t = T_ - 1 - d;
            cp_async16(&ring[1][t & (DPF - 1)][lane * 4], row0 + (size_t)t * C_ + lane * 4);
            cp_commit();
        }
        cp_wait7(); __syncwarp();
        {
            const float* rw = &ring[1][(T_ - 1) & (DPF - 1)][0];
            #pragma unroll
            for (int j = 0; j < 7; ++j) {
                int s = s0 + j;
                float w = valid[j] ? rw[cls[j]] + EPS_ : 0.f;
                a[j] = (s == 2 * L - 1 || s == 2 * L) ? w : 0.f;
            }
        }

        for (int t = T_ - 2; t >= TMID + 1; --t) {
            const int pf = t - (DPF - 1);           // >= 505
            cp_async16(&ring[1][pf & (DPF - 1)][lane * 4], row0 + (size_t)pf * C_ + lane * 4);
            cp_commit();
            cp_wait7(); __syncwarp();

            const float* rw = &ring[1][t & (DPF - 1)][0];
            float w[7];
            #pragma unroll
            for (int j = 0; j < 7; ++j)
                w[j] = valid[j] ? rw[cls[j]] + EPS_ : 0.f;

            float gd1 = __shfl_down_sync(0xffffffffu, a[0], 1);
            float gd2 = __shfl_down_sync(0xffffffffu, a[1], 1);
            float op  = __shfl_down_sync(0xffffffffu, o, 1);
            if (lane == 31) { gd1 = 0.f; gd2 = 0.f; op = o; }
            float r = ex2f(fminf(op - o, 80.f));
            gd1 *= r; gd2 *= r;

            float n[7];
            #pragma unroll
            for (int j = 0; j < 5; ++j)
                n[j] = (a[j] + a[j+1] + sk[j] * a[j+2]) * w[j];
            n[5] = (a[5] + a[6] + sk[5] * gd1) * w[5];
            n[6] = (a[6] + gd1  + sk[6] * gd2) * w[6];

            float m = n[0];
            #pragma unroll
            for (int j = 1; j < 7; ++j) m = fmaxf(m, n[j]);

            if (m > RENORM_MIN) {
                int eo; float inv = exp_scale(m, eo);
                #pragma unroll
                for (int j = 0; j < 7; ++j) a[j] = n[j] * inv;
                o += (float)eo;
            } else {
                #pragma unroll
                for (int j = 0; j < 7; ++j) a[j] = n[j];
                o = op;                                  // frame adoption
            }
        }
        cp_waitall();

        // beta_511 = band-combine(gamma_512), no emission at t=511
        {
            float gd1 = __shfl_down_sync(0xffffffffu, a[0], 1);
            float gd2 = __shfl_down_sync(0xffffffffu, a[1], 1);
            float op  = __shfl_down_sync(0xffffffffu, o, 1);
            if (lane == 31) { gd1 = 0.f; gd2 = 0.f; op = o; }
            float r = ex2f(fminf(op - o, 80.f));
            gd1 *= r; gd2 *= r;

            float d_[7];
            #pragma unroll
            for (int j = 0; j < 5; ++j)
                d_[j] = a[j] + a[j+1] + sk[j] * a[j+2];
            d_[5] = a[5] + a[6] + sk[5] * gd1;
            d_[6] = a[6] + gd1  + sk[6] * gd2;

            // exact renorm to max ~ 1: apply inv*2^-40 = 2^(-eo-40);
            // keep d*2^ob invariant via ob += eo + 40.
            float m = d_[0];
            #pragma unroll
            for (int j = 1; j < 7; ++j) m = fmaxf(m, d_[j]);
            float ob = o;
            if (m > RENORM_MIN) {
                int eo; float inv = exp_scale(m, eo);
                const float fold = 9.094947017729282e-13f;   // 2^-40 exact
                #pragma unroll
                for (int j = 0; j < 7; ++j) d_[j] = d_[j] * inv * fold;
                ob += (float)(eo + 40);
            }
            #pragma unroll
            for (int j = 0; j < 7; ++j) dbuf[lane][j] = d_[j];
            dbuf[lane][7] = ob;
        }
    }

    __syncthreads();

    if (warp == 0) {
        // P = sum_s alpha[s] * beta[s]; a ~ 2^40, d ~ O(1): no overflow
        float part = 0.f;
        const float ob = dbuf[lane][7];
        #pragma unroll
        for (int j = 0; j < 7; ++j)
            part = fmaf(a[j], dbuf[lane][j], part);
        float lp = (part > 0.f) ? (lg2f(part) + o + ob) : -3.0e38f;

        float mx = lp;
        #pragma unroll
        for (int off = 16; off; off >>= 1)
            mx = fmaxf(mx, __shfl_xor_sync(0xffffffffu, mx, off));
        float sm = ex2f(fmaxf(lp - mx, -120.f));
        #pragma unroll
        for (int off = 16; off; off >>= 1)
            sm += __shfl_xor_sync(0xffffffffu, sm, off);

        if (lane == 0)
            out[b] = -0.69314718055994531f * (mx + lg2f(sm));  // -ln P
    }
}

extern "C" void kernel_launch(void* const* d_in, const int* in_sizes, int n_in,
                              void* d_out, int out_size) {
    const float* yp = nullptr; const int* yt = nullptr; const int* ll = nullptr;
    for (int i = 0; i < n_in; ++i) {
        if (in_sizes[i] == B_ * T_ * C_)      yp = (const float*)d_in[i];
        else if (in_sizes[i] == B_ * U_)      yt = (const int*)d_in[i];
        else if (in_sizes[i] == B_)           ll = (const int*)d_in[i];
    }
    if (!yp) yp = (const float*)d_in[0];
    if (!yt) yt = (const int*)d_in[1];
    if (!ll) ll = (const int*)d_in[2];
    ctc_fb_kernel<<<B_, 64>>>(yp, yt, ll, (float*)d_out);
}

// round 11
// speedup vs baseline: 1.8402x; 1.8402x over previous
#include <cuda_runtime.h>
#include <cstdint>
#include <cstddef>

// CTC loss (keras ctc_batch_cost) on GB300. B=256,T=1024,C=128(blank=127),U=100,S=201.
//
// R10 = R7 passing numerics (103.2us, rel 7.6e-7) + overhead-only transforms:
//   - branchless renorm/adoption (select; values bit-identical to branchy form)
//   - 16-row ring, one cp.async commit per 4 rows, one wait+syncwarp per 4 steps
//   - explicit depth-3 max tree
// No changes to: per-step renorm scheme, ex2f frame conversion, clamp 80,
// init, end states, beta combine, final logsumexp.

namespace {
constexpr int B_ = 256;
constexpr int T_ = 1024;
constexpr int C_ = 128;
constexpr int U_ = 100;
constexpr int S_ = 2 * U_ + 1;      // 201
constexpr int BLANK_ = C_ - 1;      // 127
constexpr float EPS_ = 1e-7f;
constexpr int RING = 16;
constexpr float RENORM_MIN = 1e-26f;
}

__device__ __forceinline__ float ex2f(float x){ float y; asm("ex2.approx.f32 %0, %1;" : "=f"(y) : "f"(x)); return y; }
__device__ __forceinline__ float lg2f(float x){ float y; asm("lg2.approx.f32 %0, %1;" : "=f"(y) : "f"(x)); return y; }

// exact renorm: inv = 2^-eo with m*inv ~ [2^40,2^41); exponent clamped to [1,254]
__device__ __forceinline__ float exp_scale(float m, int& eo){
    int ei = (__float_as_int(m) >> 23) & 0xff;
    int eb = 294 - ei;
    eb = (eb < 1) ? 1 : (eb > 254 ? 254 : eb);
    eo = 127 - eb;
    return __int_as_float(eb << 23);
}

__device__ __forceinline__ void cp_async16(void* sdst, const void* gsrc){
    uint32_t s;
    asm("{ .reg .u64 t; cvta.to.shared.u64 t, %1; cvt.u32.u64 %0, t; }" : "=r"(s) : "l"(sdst));
    asm volatile("cp.async.cg.shared.global [%0], [%1], 16;" :: "r"(s), "l"(gsrc));
}
__device__ __forceinline__ void cp_commit(){ asm volatile("cp.async.commit_group;" ::: "memory"); }
__device__ __forceinline__ void cp_wait3(){ asm volatile("cp.async.wait_group 3;" ::: "memory"); }
__device__ __forceinline__ void cp_waitall(){ asm volatile("cp.async.wait_all;" ::: "memory"); }

__global__ void __launch_bounds__(64)
ctc_fb_kernel(const float* __restrict__ yp, const int* __restrict__ yt,
              const int* __restrict__ llen, float* __restrict__ out)
{
    __shared__ float ring[2][RING][C_];
    __shared__ float dbuf[32][8];

    const int b    = blockIdx.x;
    const int warp = threadIdx.x >> 5;
    const int lane = threadIdx.x & 31;
    const float* __restrict__ row0 = yp + (size_t)b * T_ * C_;
    const int*   __restrict__ lab  = yt + b * U_;
    const int L = llen[b];

    const int s0 = lane * 7;
    int   cls[7];
    float sk[7];
    bool  valid[7];
    #pragma unroll
    for (int j = 0; j < 7; ++j) {
        int s = s0 + j;
        valid[j] = (s < S_);
        int c = BLANK_;
        if (valid[j] && (s & 1)) c = lab[s >> 1];
        cls[j] = c;
        if (warp == 0) {
            sk[j] = (valid[j] && (s & 1) && s >= 3 && lab[s >> 1] != lab[(s >> 1) - 1]) ? 1.f : 0.f;
        } else {
            int s2 = s + 2;
            sk[j] = ((s2 < S_) && (s2 & 1) && lab[s2 >> 1] != lab[(s2 >> 1) - 1]) ? 1.f : 0.f;
        }
    }

    float a[7];
    float o = 0.f;   // per-lane log2 offset (integer-valued): true value = a[j]*2^o

    if (warp == 0) {
        // =========================== FORWARD ===========================
        auto stepF = [&](const float* __restrict__ rw){
            float am1 = __shfl_up_sync(0xffffffffu, a[6], 1);
            float am2 = __shfl_up_sync(0xffffffffu, a[5], 1);
            float op  = __shfl_up_sync(0xffffffffu, o, 1);
            if (lane == 0) { am1 = 0.f; am2 = 0.f; op = o; }
            float r = ex2f(fminf(op - o, 80.f));
            am1 *= r; am2 *= r;

            float w[7];
            #pragma unroll
            for (int j = 0; j < 7; ++j)
                w[j] = valid[j] ? rw[cls[j]] + EPS_ : 0.f;

            float n0 = (a[0] + am1  + sk[0] * am2 ) * w[0];
            float n1 = (a[1] + a[0] + sk[1] * am1 ) * w[1];
            float n2 = (a[2] + a[1] + sk[2] * a[0]) * w[2];
            float n3 = (a[3] + a[2] + sk[3] * a[1]) * w[3];
            float n4 = (a[4] + a[3] + sk[4] * a[2]) * w[4];
            float n5 = (a[5] + a[4] + sk[5] * a[3]) * w[5];
            float n6 = (a[6] + a[5] + sk[6] * a[4]) * w[6];

            float m01 = fmaxf(n0, n1), m23 = fmaxf(n2, n3);
            float m45 = fmaxf(n4, n5);
            float m = fmaxf(fmaxf(m01, m23), fmaxf(m45, n6));

            bool hm = m > RENORM_MIN;
            int eo; float inv = exp_scale(m, eo);
            float invs = hm ? inv : 1.0f;            // *1.0f exact -> branchless
            o = hm ? o + (float)eo : op;             // adoption when empty
            a[0] = n0*invs; a[1] = n1*invs; a[2] = n2*invs; a[3] = n3*invs;
            a[4] = n4*invs; a[5] = n5*invs; a[6] = n6*invs;
        };

        #pragma unroll
        for (int g = 0; g < 4; ++g){
            #pragma unroll
            for (int i = 0; i < 4; ++i)
                cp_async16(&ring[0][g*4+i][lane*4], row0 + (size_t)(g*4+i)*C_ + lane*4);
            cp_commit();
        }
        cp_wait3(); __syncwarp();

        { // t = 0 init
            const float* rw = &ring[0][0][0];
            #pragma unroll
            for (int j = 0; j < 7; ++j){
                float w = valid[j] ? rw[cls[j]] + EPS_ : 0.f;
                a[j] = (s0 + j <= 1) ? w : 0.f;
            }
        }
        stepF(&ring[0][1][0]); stepF(&ring[0][2][0]); stepF(&ring[0][3][0]);
        #pragma unroll
        for (int i = 0; i < 4; ++i)
            cp_async16(&ring[0][(16+i)&15][lane*4], row0 + (size_t)(16+i)*C_ + lane*4);
        cp_commit();

        for (int k = 1; k < 128; ++k){            // steps t = 4k .. 4k+3, ends at 511
            cp_wait3(); __syncwarp();
            const float* p = &ring[0][(k & 3) * 4][0];
            stepF(p); stepF(p + C_); stepF(p + 2*C_); stepF(p + 3*C_);
            const int pf = 4*k + 16;              // <= 527 < 1024
            #pragma unroll
            for (int i = 0; i < 4; ++i)
                cp_async16(&ring[0][(pf+i)&15][lane*4], row0 + (size_t)(pf+i)*C_ + lane*4);
            cp_commit();
        }
        cp_waitall();
    } else {
        // =========================== BACKWARD ==========================
        auto stepB = [&](const float* __restrict__ rw){
            float gd1 = __shfl_down_sync(0xffffffffu, a[0], 1);
            float gd2 = __shfl_down_sync(0xffffffffu, a[1], 1);
            float op  = __shfl_down_sync(0xffffffffu, o, 1);
            if (lane == 31) { gd1 = 0.f; gd2 = 0.f; op = o; }
            float r = ex2f(fminf(op - o, 80.f));
            gd1 *= r; gd2 *= r;

            float w[7];
            #pragma unroll
            for (int j = 0; j < 7; ++j)
                w[j] = valid[j] ? rw[cls[j]] + EPS_ : 0.f;

            float n0 = (a[0] + a[1] + sk[0] * a[2]) * w[0];
            float n1 = (a[1] + a[2] + sk[1] * a[3]) * w[1];
            float n2 = (a[2] + a[3] + sk[2] * a[4]) * w[2];
            float n3 = (a[3] + a[4] + sk[3] * a[5]) * w[3];
            float n4 = (a[4] + a[5] + sk[4] * a[6]) * w[4];
            float n5 = (a[5] + a[6] + sk[5] * gd1 ) * w[5];
            float n6 = (a[6] + gd1  + sk[6] * gd2 ) * w[6];

            float m01 = fmaxf(n0, n1), m23 = fmaxf(n2, n3);
            float m45 = fmaxf(n4, n5);
            float m = fmaxf(fmaxf(m01, m23), fmaxf(m45, n6));

            bool hm = m > RENORM_MIN;
            int eo; float inv = exp_scale(m, eo);
            float invs = hm ? inv : 1.0f;
            o = hm ? o + (float)eo : op;
            a[0] = n0*invs; a[1] = n1*invs; a[2] = n2*invs; a[3] = n3*invs;
            a[4] = n4*invs; a[5] = n5*invs; a[6] = n6*invs;
        };

        #pragma unroll
        for (int g = 0; g < 4; ++g){
            const int G = 1020 - 4*g;
            #pragma unroll
            for (int i = 0; i < 4; ++i)
                cp_async16(&ring[1][(G+i)&15][lane*4], row0 + (size_t)(G+i)*C_ + lane*4);
            cp_commit();
        }
        cp_wait3(); __syncwarp();

        { // t = 1023 init (end states 2L-1, 2L)
            const float* rw = &ring[1][1023 & 15][0];
            #pragma unroll
            for (int j = 0; j < 7; ++j){
                int s = s0 + j;
                float w = valid[j] ? rw[cls[j]] + EPS_ : 0.f;
                a[j] = (s == 2*L - 1 || s == 2*L) ? w : 0.f;
            }
        }
        stepB(&ring[1][1022 & 15][0]); stepB(&ring[1][1021 & 15][0]); stepB(&ring[1][1020 & 15][0]);
        #pragma unroll
        for (int i = 0; i < 4; ++i)
            cp_async16(&ring[1][(1004+i)&15][lane*4], row0 + (size_t)(1004+i)*C_ + lane*4);
        cp_commit();

        for (int k = 1; k < 128; ++k){            // steps t = G+3 .. G, G = 1020-4k; ends at 512
            cp_wait3(); __syncwarp();
            const int G = 1020 - 4*k;
            const float* p = &ring[1][G & 15][0];
            stepB(p + 3*C_); stepB(p + 2*C_); stepB(p + C_); stepB(p);
            const int pf = G - 16;                // >= 496
            #pragma unroll
            for (int i = 0; i < 4; ++i)
                cp_async16(&ring[1][(pf+i)&15][lane*4], row0 + (size_t)(pf+i)*C_ + lane*4);
            cp_commit();
        }
        cp_waitall();

        // beta_511 = band-combine(gamma_512), no emission at t=511 (R7 verbatim)
        {
            float gd1 = __shfl_down_sync(0xffffffffu, a[0], 1);
            float gd2 = __shfl_down_sync(0xffffffffu, a[1], 1);
            float op  = __shfl_down_sync(0xffffffffu, o, 1);
            if (lane == 31) { gd1 = 0.f; gd2 = 0.f; op = o; }
            float r = ex2f(fminf(op - o, 80.f));
            gd1 *= r; gd2 *= r;

            float d_[7];
            #pragma unroll
            for (int j = 0; j < 5; ++j)
                d_[j] = a[j] + a[j+1] + sk[j] * a[j+2];
            d_[5] = a[5] + a[6] + sk[5] * gd1;
            d_[6] = a[6] + gd1  + sk[6] * gd2;

            float m = d_[0];
            #pragma unroll
            for (int j = 1; j < 7; ++j) m = fmaxf(m, d_[j]);
            float ob = o;
            if (m > RENORM_MIN) {
                int eo; float inv = exp_scale(m, eo);
                const float fold = 9.094947017729282e-13f;   // 2^-40 exact
                #pragma unroll
                for (int j = 0; j < 7; ++j) d_[j] = d_[j] * inv * fold;
                ob += (float)(eo + 40);
            }
            #pragma unroll
            for (int j = 0; j < 7; ++j) dbuf[lane][j] = d_[j];
            dbuf[lane][7] = ob;
        }
    }

    __syncthreads();

    if (warp == 0) {
        // P = sum_s alpha_511[s] * beta_511[s]; a ~ 2^40, d ~ O(1)
        float part = 0.f;
        const float ob = dbuf[lane][7];
        #pragma unroll
        for (int j = 0; j < 7; ++j)
            part = fmaf(a[j], dbuf[lane][j], part);
        float lp = (part > 0.f) ? (lg2f(part) + o + ob) : -3.0e38f;

        float mx = lp;
        #pragma unroll
        for (int off = 16; off; off >>= 1)
            mx = fmaxf(mx, __shfl_xor_sync(0xffffffffu, mx, off));
        float sm = ex2f(fmaxf(lp - mx, -120.f));
        #pragma unroll
        for (int off = 16; off; off >>= 1)
            sm += __shfl_xor_sync(0xffffffffu, sm, off);

        if (lane == 0)
            out[b] = -0.69314718055994531f * (mx + lg2f(sm));  // -ln P
    }
}

extern "C" void kernel_launch(void* const* d_in, const int* in_sizes, int n_in,
                              void* d_out, int out_size) {
    const float* yp = nullptr; const int* yt = nullptr; const int* ll = nullptr;
    for (int i = 0; i < n_in; ++i) {
        if (in_sizes[i] == B_ * T_ * C_)      yp = (const float*)d_in[i];
        else if (in_sizes[i] == B_ * U_)      yt = (const int*)d_in[i];
        else if (in_sizes[i] == B_)           ll = (const int*)d_in[i];
    }
    if (!yp) yp = (const float*)d_in[0];
    if (!yt) yt = (const int*)d_in[1];
    if (!ll) ll = (const int*)d_in[2];
    ctc_fb_kernel<<<B_, 64>>>(yp, yt, ll, (float*)d_out);
}

// round 16
// speedup vs baseline: 2.5227x; 1.3709x over previous
#include <cuda_runtime.h>
#include <cstdint>
#include <cstddef>

// CTC loss (keras ctc_batch_cost) on GB300. B=256,T=1024,C=128(blank=127),U=100,S=201.
//
// R11 = R10 (56.1us, rel 7.6e-7) + instruction-count cuts (all exact-power-of-2
// safe; mass-lane values bit-equivalent):
//   - renorm every 2nd step (pair structure); range stays in [2^-6, 2^126]
//   - frame conversion (shfl op + fmin + ex2) hoisted to once per pair
//   - w gather via single fmaf with {0,1} mask (same rounding as FADD+SEL)

namespace {
constexpr int B_ = 256;
constexpr int T_ = 1024;
constexpr int C_ = 128;
constexpr int U_ = 100;
constexpr int S_ = 2 * U_ + 1;      // 201
constexpr int BLANK_ = C_ - 1;      // 127
constexpr float EPS_ = 1e-7f;
constexpr int RING = 16;
constexpr float RENORM_MIN = 1e-26f;
}

__device__ __forceinline__ float ex2f(float x){ float y; asm("ex2.approx.f32 %0, %1;" : "=f"(y) : "f"(x)); return y; }
__device__ __forceinline__ float lg2f(float x){ float y; asm("lg2.approx.f32 %0, %1;" : "=f"(y) : "f"(x)); return y; }

// exact renorm: inv = 2^-eo with m*inv ~ [2^40,2^41); exponent clamped to [1,254]
__device__ __forceinline__ float exp_scale(float m, int& eo){
    int ei = (__float_as_int(m) >> 23) & 0xff;
    int eb = 294 - ei;
    eb = (eb < 1) ? 1 : (eb > 254 ? 254 : eb);
    eo = 127 - eb;
    return __int_as_float(eb << 23);
}

__device__ __forceinline__ void cp_async16(void* sdst, const void* gsrc){
    uint32_t s;
    asm("{ .reg .u64 t; cvta.to.shared.u64 t, %1; cvt.u32.u64 %0, t; }" : "=r"(s) : "l"(sdst));
    asm volatile("cp.async.cg.shared.global [%0], [%1], 16;" :: "r"(s), "l"(gsrc));
}
__device__ __forceinline__ void cp_commit(){ asm volatile("cp.async.commit_group;" ::: "memory"); }
__device__ __forceinline__ void cp_wait3(){ asm volatile("cp.async.wait_group 3;" ::: "memory"); }
__device__ __forceinline__ void cp_waitall(){ asm volatile("cp.async.wait_all;" ::: "memory"); }

__global__ void __launch_bounds__(64)
ctc_fb_kernel(const float* __restrict__ yp, const int* __restrict__ yt,
              const int* __restrict__ llen, float* __restrict__ out)
{
    __shared__ float ring[2][RING][C_];
    __shared__ float dbuf[32][8];

    const int b    = blockIdx.x;
    const int warp = threadIdx.x >> 5;
    const int lane = threadIdx.x & 31;
    const float* __restrict__ row0 = yp + (size_t)b * T_ * C_;
    const int*   __restrict__ lab  = yt + b * U_;
    const int L = llen[b];

    const int s0 = lane * 7;
    int   cls[7];
    float sk[7];
    float vm[7];     // 1.0 valid / 0.0 invalid
    float ev[7];     // EPS * vm
    #pragma unroll
    for (int j = 0; j < 7; ++j) {
        int s = s0 + j;
        bool v = (s < S_);
        int c = BLANK_;
        if (v && (s & 1)) c = lab[s >> 1];
        cls[j] = c;
        vm[j] = v ? 1.f : 0.f;
        ev[j] = v ? EPS_ : 0.f;
        if (warp == 0) {
            sk[j] = (v && (s & 1) && s >= 3 && lab[s >> 1] != lab[(s >> 1) - 1]) ? 1.f : 0.f;
        } else {
            int s2 = s + 2;
            sk[j] = ((s2 < S_) && (s2 & 1) && lab[s2 >> 1] != lab[(s2 >> 1) - 1]) ? 1.f : 0.f;
        }
    }

    float a[7];
    float o = 0.f;     // integer-valued log2 offset: true value = a[j]*2^o
    float r_c = 1.f;   // per-pair cached frame conversion 2^(op-o)
    float op_c = 0.f;  // per-pair cached neighbor offset

    if (warp == 0) {
        // =========================== FORWARD ===========================
        auto frameF = [&](){
            float op = __shfl_up_sync(0xffffffffu, o, 1);
            if (lane == 0) op = o;
            op_c = op;
            r_c = ex2f(fminf(op - o, 80.f));
        };
        auto bandF = [&](const float* __restrict__ rw, float* n){
            float am1 = __shfl_up_sync(0xffffffffu, a[6], 1);
            float am2 = __shfl_up_sync(0xffffffffu, a[5], 1);
            if (lane == 0) { am1 = 0.f; am2 = 0.f; }
            am1 *= r_c; am2 *= r_c;
            float w[7];
            #pragma unroll
            for (int j = 0; j < 7; ++j)
                w[j] = fmaf(rw[cls[j]], vm[j], ev[j]);
            n[0] = (a[0] + am1  + sk[0] * am2 ) * w[0];
            n[1] = (a[1] + a[0] + sk[1] * am1 ) * w[1];
            n[2] = (a[2] + a[1] + sk[2] * a[0]) * w[2];
            n[3] = (a[3] + a[2] + sk[3] * a[1]) * w[3];
            n[4] = (a[4] + a[3] + sk[4] * a[2]) * w[4];
            n[5] = (a[5] + a[4] + sk[5] * a[3]) * w[5];
            n[6] = (a[6] + a[5] + sk[6] * a[4]) * w[6];
        };
        auto renorm = [&](const float* n){
            float m01 = fmaxf(n[0], n[1]), m23 = fmaxf(n[2], n[3]);
            float m45 = fmaxf(n[4], n[5]);
            float m = fmaxf(fmaxf(m01, m23), fmaxf(m45, n[6]));
            bool hm = m > RENORM_MIN;
            int eo; float inv = exp_scale(m, eo);
            float invs = hm ? inv : 1.0f;
            o = hm ? o + (float)eo : op_c;
            #pragma unroll
            for (int j = 0; j < 7; ++j) a[j] = n[j] * invs;
        };
        auto pairF = [&](const float* rwA, const float* rwB){
            frameF();
            float n[7];
            bandF(rwA, n);
            #pragma unroll
            for (int j = 0; j < 7; ++j) a[j] = n[j];   // no renorm mid-pair
            bandF(rwB, n);
            renorm(n);
        };
        auto stepFullF = [&](const float* rw){
            frameF();
            float n[7];
            bandF(rw, n);
            renorm(n);
        };

        #pragma unroll
        for (int g = 0; g < 4; ++g){
            #pragma unroll
            for (int i = 0; i < 4; ++i)
                cp_async16(&ring[0][g*4+i][lane*4], row0 + (size_t)(g*4+i)*C_ + lane*4);
            cp_commit();
        }
        cp_wait3(); __syncwarp();

        { // t = 0 init
            const float* rw = &ring[0][0][0];
            #pragma unroll
            for (int j = 0; j < 7; ++j){
                float w = fmaf(rw[cls[j]], vm[j], ev[j]);
                a[j] = (s0 + j <= 1) ? w : 0.f;
            }
        }
        pairF(&ring[0][1][0], &ring[0][2][0]);
        stepFullF(&ring[0][3][0]);
        #pragma unroll
        for (int i = 0; i < 4; ++i)
            cp_async16(&ring[0][(16+i)&15][lane*4], row0 + (size_t)(16+i)*C_ + lane*4);
        cp_commit();

        for (int k = 1; k < 128; ++k){            // steps t = 4k .. 4k+3, ends at 511
            cp_wait3(); __syncwarp();
            const float* p = &ring[0][(k & 3) * 4][0];
            pairF(p, p + C_);
            pairF(p + 2*C_, p + 3*C_);
            const int pf = 4*k + 16;              // <= 527 < 1024
            #pragma unroll
            for (int i = 0; i < 4; ++i)
                cp_async16(&ring[0][(pf+i)&15][lane*4], row0 + (size_t)(pf+i)*C_ + lane*4);
            cp_commit();
        }
        cp_waitall();
    } else {
        // =========================== BACKWARD ==========================
        auto frameB = [&](){
            float op = __shfl_down_sync(0xffffffffu, o, 1);
            if (lane == 31) op = o;
            op_c = op;
            r_c = ex2f(fminf(op - o, 80.f));
        };
        auto bandB = [&](const float* __restrict__ rw, float* n){
            float gd1 = __shfl_down_sync(0xffffffffu, a[0], 1);
            float gd2 = __shfl_down_sync(0xffffffffu, a[1], 1);
            if (lane == 31) { gd1 = 0.f; gd2 = 0.f; }
            gd1 *= r_c; gd2 *= r_c;
            float w[7];
            #pragma unroll
            for (int j = 0; j < 7; ++j)
                w[j] = fmaf(rw[cls[j]], vm[j], ev[j]);
            n[0] = (a[0] + a[1] + sk[0] * a[2]) * w[0];
            n[1] = (a[1] + a[2] + sk[1] * a[3]) * w[1];
            n[2] = (a[2] + a[3] + sk[2] * a[4]) * w[2];
            n[3] = (a[3] + a[4] + sk[3] * a[5]) * w[3];
            n[4] = (a[4] + a[5] + sk[4] * a[6]) * w[4];
            n[5] = (a[5] + a[6] + sk[5] * gd1 ) * w[5];
            n[6] = (a[6] + gd1  + sk[6] * gd2 ) * w[6];
        };
        auto renorm = [&](const float* n){
            float m01 = fmaxf(n[0], n[1]), m23 = fmaxf(n[2], n[3]);
            float m45 = fmaxf(n[4], n[5]);
            float m = fmaxf(fmaxf(m01, m23), fmaxf(m45, n[6]));
            bool hm = m > RENORM_MIN;
            int eo; float inv = exp_scale(m, eo);
            float invs = hm ? inv : 1.0f;
            o = hm ? o + (float)eo : op_c;
            #pragma unroll
            for (int j = 0; j < 7; ++j) a[j] = n[j] * invs;
        };
        auto pairB = [&](const float* rwA, const float* rwB){
            frameB();
            float n[7];
            bandB(rwA, n);
            #pragma unroll
            for (int j = 0; j < 7; ++j) a[j] = n[j];
            bandB(rwB, n);
            renorm(n);
        };
        auto stepFullB = [&](const float* rw){
            frameB();
            float n[7];
            bandB(rw, n);
            renorm(n);
        };

        #pragma unroll
        for (int g = 0; g < 4; ++g){
            const int G = 1020 - 4*g;
            #pragma unroll
            for (int i = 0; i < 4; ++i)
                cp_async16(&ring[1][(G+i)&15][lane*4], row0 + (size_t)(G+i)*C_ + lane*4);
            cp_commit();
        }
        cp_wait3(); __syncwarp();

        { // t = 1023 init (end states 2L-1, 2L)
            const float* rw = &ring[1][1023 & 15][0];
            #pragma unroll
            for (int j = 0; j < 7; ++j){
                int s = s0 + j;
                float w = fmaf(rw[cls[j]], vm[j], ev[j]);
                a[j] = (s == 2*L - 1 || s == 2*L) ? w : 0.f;
            }
        }
        pairB(&ring[1][1022 & 15][0], &ring[1][1021 & 15][0]);
        stepFullB(&ring[1][1020 & 15][0]);
        #pragma unroll
        for (int i = 0; i < 4; ++i)
            cp_async16(&ring[1][(1004+i)&15][lane*4], row0 + (size_t)(1004+i)*C_ + lane*4);
        cp_commit();

        for (int k = 1; k < 128; ++k){            // steps t = G+3 .. G, G = 1020-4k; ends at 512
            cp_wait3(); __syncwarp();
            const int G = 1020 - 4*k;
            const float* p = &ring[1][G & 15][0];
            pairB(p + 3*C_, p + 2*C_);
            pairB(p + C_,   p);
            const int pf = G - 16;                // >= 496
            #pragma unroll
            for (int i = 0; i < 4; ++i)
                cp_async16(&ring[1][(pf+i)&15][lane*4], row0 + (size_t)(pf+i)*C_ + lane*4);
            cp_commit();
        }
        cp_waitall();

        // beta_511 = band-combine(gamma_512), no emission at t=511 (R10 verbatim)
        {
            float gd1 = __shfl_down_sync(0xffffffffu, a[0], 1);
            float gd2 = __shfl_down_sync(0xffffffffu, a[1], 1);
            float op  = __shfl_down_sync(0xffffffffu, o, 1);
            if (lane == 31) { gd1 = 0.f; gd2 = 0.f; op = o; }
            float r = ex2f(fminf(op - o, 80.f));
            gd1 *= r; gd2 *= r;

            float d_[7];
            #pragma unroll
            for (int j = 0; j < 5; ++j)
                d_[j] = a[j] + a[j+1] + sk[j] * a[j+2];
            d_[5] = a[5] + a[6] + sk[5] * gd1;
            d_[6] = a[6] + gd1  + sk[6] * gd2;

            float m = d_[0];
            #pragma unroll
            for (int j = 1; j < 7; ++j) m = fmaxf(m, d_[j]);
            float ob = o;
            if (m > RENORM_MIN) {
                int eo; float inv = exp_scale(m, eo);
                const float fold = 9.094947017729282e-13f;   // 2^-40 exact
                #pragma unroll
                for (int j = 0; j < 7; ++j) d_[j] = d_[j] * inv * fold;
                ob += (float)(eo + 40);
            }
            #pragma unroll
            for (int j = 0; j < 7; ++j) dbuf[lane][j] = d_[j];
            dbuf[lane][7] = ob;
        }
    }

    __syncthreads();

    if (warp == 0) {
        // P = sum_s alpha_511[s] * beta_511[s]
        float part = 0.f;
        const float ob = dbuf[lane][7];
        #pragma unroll
        for (int j = 0; j < 7; ++j)
            part = fmaf(a[j], dbuf[lane][j], part);
        float lp = (part > 0.f) ? (lg2f(part) + o + ob) : -3.0e38f;

        float mx = lp;
        #pragma unroll
        for (int off = 16; off; off >>= 1)
            mx = fmaxf(mx, __shfl_xor_sync(0xffffffffu, mx, off));
        float sm = ex2f(fmaxf(lp - mx, -120.f));
        #pragma unroll
        for (int off = 16; off; off >>= 1)
            sm += __shfl_xor_sync(0xffffffffu, sm, off);

        if (lane == 0)
            out[b] = -0.69314718055994531f * (mx + lg2f(sm));  // -ln P
    }
}

extern "C" void kernel_launch(void* const* d_in, const int* in_sizes, int n_in,
                              void* d_out, int out_size) {
    const float* yp = nullptr; const int* yt = nullptr; const int* ll = nullptr;
    for (int i = 0; i < n_in; ++i) {
        if (in_sizes[i] == B_ * T_ * C_)      yp = (const float*)d_in[i];
        else if (in_sizes[i] == B_ * U_)      yt = (const int*)d_in[i];
        else if (in_sizes[i] == B_)           ll = (const int*)d_in[i];
    }
    if (!yp) yp = (const float*)d_in[0];
    if (!yt) yt = (const int*)d_in[1];
    if (!ll) ll = (const int*)d_in[2];
    ctc_fb_kernel<<<B_, 64>>>(yp, yt, ll, (float*)d_out);
}